// round 13
// baseline (speedup 1.0000x reference)
#include <cuda_runtime.h>
#include <math.h>

#define Bn    128
#define Tn    128
#define In    512
#define Hn    512
#define Dn    1024
#define Nn    513
#define NP    576
#define DEPTH 4
#define EPSV  1e-5f
#define NCTA  148
#define NTHR  256
#define KS    16
#define SCTA  144      // KS * 9 strips

typedef unsigned long long u64t;

// ----------------------------- device state --------------------------------
__device__ float g_Wp[Dn * NP];
__device__ float g_Up[Dn * NP];
__device__ float g_XA[(size_t)Tn * Dn * Bn];   // x/h history, [t][d][b], ping
__device__ float g_XB[(size_t)Tn * Dn * Bn];   // pong
__device__ float g_XWraw[Tn * Bn * NP];
__device__ float g_spre[Tn * Bn * NP];
__device__ float g_Gpart[Bn * KS * NP];        // [b][ks][NP] contiguous per batch
__device__ float g_h[Bn * Dn];                 // tanh region live; x region unused
__device__ float2 g_gates[Bn];                 // {A_b, B_b} per batch
__device__ float g_fkseq[Tn * Bn];
__device__ float g_hvseq[Tn * Bn];
__device__ unsigned g_ctr;
__device__ unsigned g_pCnt, g_pEp;

// --------------------------- f32x2 packed math ------------------------------
__device__ __forceinline__ void ffma2(u64t& d, u64t a, u64t b) {
    asm("fma.rn.f32x2 %0, %1, %2, %0;" : "+l"(d) : "l"(a), "l"(b));
}
__device__ __forceinline__ u64t packdup(float x) {
    u64t r; asm("mov.b64 %0, {%1, %1};" : "=l"(r) : "f"(x)); return r;
}
__device__ __forceinline__ float2 unpack2(u64t v) {
    float2 f; asm("mov.b64 {%0, %1}, %2;" : "=f"(f.x), "=f"(f.y) : "l"(v)); return f;
}

// ------------------------------ barriers ------------------------------------
__device__ __forceinline__ unsigned ld_acq(unsigned* p) {
    unsigned v;
    asm volatile("ld.acquire.gpu.u32 %0, [%1];" : "=r"(v) : "l"(p) : "memory");
    return v;
}
__device__ __forceinline__ void prep_barrier(unsigned& ep) {
    __syncthreads();
    if (threadIdx.x == 0) {
        ep += 1;
        __threadfence();
        unsigned prev = atomicAdd(&g_pCnt, 1u);
        if (prev == (unsigned)(NCTA - 1)) {
            atomicExch(&g_pCnt, 0u);
            __threadfence();
            atomicExch(&g_pEp, ep);
        } else {
            while (ld_acq(&g_pEp) < ep) { }
        }
        __threadfence();
    }
    __syncthreads();
}
__device__ __forceinline__ void bar_arrive(unsigned& k) {
    __syncthreads();
    if (threadIdx.x == 0) {
        k += (unsigned)NCTA;
        __threadfence();
        asm volatile("red.release.gpu.add.u32 [%0], 1;" :: "l"(&g_ctr) : "memory");
    }
}
__device__ __forceinline__ void bar_wait(unsigned base, unsigned k) {
    if (threadIdx.x == 0) {
        while ((unsigned)(ld_acq(&g_ctr) - base) < k) { }
        __threadfence();
    }
    __syncthreads();
}

// ------------------- staging helpers (256 threads) --------------------------
// direct copy: 64 rows x 128 cols from [d][b]-layout global into hT (stride 132)
__device__ __forceinline__ void stage_direct(float* hT, const float* src) {
    int tid = threadIdx.x;
    int kr = tid >> 2, bq = (tid & 3) << 5;
    const float* s = src + (size_t)kr * Bn + bq;
    float* d = hT + kr * 132 + bq;
#pragma unroll
    for (int q = 0; q < 8; q++)
        *(float4*)(d + (q << 2)) = *(const float4*)(s + (q << 2));
}
// transpose stage: A[row][k] (lda) -> hT[k][row] (stride 132)
__device__ __forceinline__ void stage_T(float* hT, const float* A, int lda, int k0) {
    int tid = threadIdx.x;
    int row = tid & 127;
    int kh  = (tid >> 7) << 5;
    const float* src = A + (size_t)row * lda + k0 + kh;
#pragma unroll
    for (int q = 0; q < 8; q++) {
        float4 v = *(const float4*)(src + (q << 2));
        int k = kh + (q << 2);
        hT[(k + 0) * 132 + row] = v.x;
        hT[(k + 1) * 132 + row] = v.y;
        hT[(k + 2) * 132 + row] = v.z;
        hT[(k + 3) * 132 + row] = v.w;
    }
}
// B chunk: 64 k x 64 cols (row stride NP) -> Usm[k*64 + c]
__device__ __forceinline__ void stage_B(float* Usm, const float* Bg, int k0, int n0) {
    int tid = threadIdx.x;
    int kr = tid >> 2;
    int cq = (tid & 3) << 4;
    const float* src = Bg + (size_t)(k0 + kr) * NP + n0 + cq;
#pragma unroll
    for (int q = 0; q < 4; q++)
        *(float4*)&Usm[(kr << 6) + cq + (q << 2)] = *(const float4*)(src + (q << 2));
}

// ---------------- 128x64 GEMM chunk (tid<128, 8x8 microtile) ----------------
__device__ __forceinline__ void gemm_chunk(u64t acc[8][4], const float* hT,
                                           const float* Usm, int ty, int tx) {
#pragma unroll 8
    for (int kk = 0; kk < 64; kk++) {
        const float* ap = hT + kk * 132 + (ty << 3);
        float4 a0 = *(const float4*)ap;
        float4 a1 = *(const float4*)(ap + 4);
        const u64t* up = (const u64t*)(Usm + (kk << 6) + (tx << 3));
        u64t b0 = up[0], b1 = up[1], b2 = up[2], b3 = up[3];
        u64t ad;
        ad = packdup(a0.x); ffma2(acc[0][0], ad, b0); ffma2(acc[0][1], ad, b1);
                            ffma2(acc[0][2], ad, b2); ffma2(acc[0][3], ad, b3);
        ad = packdup(a0.y); ffma2(acc[1][0], ad, b0); ffma2(acc[1][1], ad, b1);
                            ffma2(acc[1][2], ad, b2); ffma2(acc[1][3], ad, b3);
        ad = packdup(a0.z); ffma2(acc[2][0], ad, b0); ffma2(acc[2][1], ad, b1);
                            ffma2(acc[2][2], ad, b2); ffma2(acc[2][3], ad, b3);
        ad = packdup(a0.w); ffma2(acc[3][0], ad, b0); ffma2(acc[3][1], ad, b1);
                            ffma2(acc[3][2], ad, b2); ffma2(acc[3][3], ad, b3);
        ad = packdup(a1.x); ffma2(acc[4][0], ad, b0); ffma2(acc[4][1], ad, b1);
                            ffma2(acc[4][2], ad, b2); ffma2(acc[4][3], ad, b3);
        ad = packdup(a1.y); ffma2(acc[5][0], ad, b0); ffma2(acc[5][1], ad, b1);
                            ffma2(acc[5][2], ad, b2); ffma2(acc[5][3], ad, b3);
        ad = packdup(a1.z); ffma2(acc[6][0], ad, b0); ffma2(acc[6][1], ad, b1);
                            ffma2(acc[6][2], ad, b2); ffma2(acc[6][3], ad, b3);
        ad = packdup(a1.w); ffma2(acc[7][0], ad, b0); ffma2(acc[7][1], ad, b1);
                            ffma2(acc[7][2], ad, b2); ffma2(acc[7][3], ad, b3);
    }
}
__device__ __forceinline__ void write_tile(u64t acc[8][4], float* C, int ldc,
                                           int ty, int tx) {
#pragma unroll
    for (int i = 0; i < 8; i++) {
        float2 p0 = unpack2(acc[i][0]), p1 = unpack2(acc[i][1]);
        float2 p2 = unpack2(acc[i][2]), p3 = unpack2(acc[i][3]);
        float* cp = C + (size_t)((ty << 3) + i) * ldc + (tx << 3);
        *(float4*)cp       = make_float4(p0.x, p0.y, p1.x, p1.y);
        *(float4*)(cp + 4) = make_float4(p2.x, p2.y, p3.x, p3.y);
    }
}

// ------------------------------ main kernel ---------------------------------
__global__ void __launch_bounds__(NTHR, 1) hrnn_kernel(
    const float* __restrict__ x, const int* __restrict__ mask,
    const float* __restrict__ W, const float* __restrict__ U,
    const float* __restrict__ bias, const float* __restrict__ gam,
    const float* __restrict__ bet, float* __restrict__ out)
{
    __shared__ __align__(16) float sh_U[64 * 64];
    __shared__ __align__(16) float sh_hT[64 * 132];
    __shared__ float sh_s[Nn];
    __shared__ float sh_red[16];
    __shared__ float sh_sc[8];
    __shared__ float sh_gA[Bn], sh_gB[Bn];

    int cta = blockIdx.x, tid = threadIdx.x;
    int gtid = cta * NTHR + tid;
    const int nthr = NCTA * NTHR;

    // ------------------------------- prep -----------------------------------
    for (size_t i = gtid; i < (size_t)Tn * Dn * Bn; i += nthr) {
        int b = (int)(i & 127);
        int d = (int)((i >> 7) & 1023);
        int t = (int)(i >> 17);
        g_XA[i] = (d < In) ? x[((size_t)b * Tn + t) * In + d] : 0.f;
    }
    for (int i = gtid; i < Dn * NP; i += nthr) {
        int col = i % NP, r = i / NP;
        float wv = 0.f, uv = 0.f;
        if (col < Nn) { wv = W[r * Nn + col]; uv = U[r * Nn + col]; }
        g_Wp[i] = wv;
        g_Up[i] = uv;
    }
    for (int i = gtid; i < Tn * Bn; i += nthr) { g_fkseq[i] = 0.f; g_hvseq[i] = 1.f; }

    unsigned base = 0, kbar = 0, epP = 0;
    if (tid == 0) {
        base = ld_acq(&g_ctr);
        epP  = ld_acq(&g_pEp);
    }
    prep_barrier(epP);

    const float* gam0 = gam;
    const float* gam1 = gam + Nn;
    const float* bet0 = bet;
    const float* bet1 = bet + Nn;

    // hoisted LN-1 constants (level-invariant)
    float g1a = gam1[tid], b1a = bet1[tid];
    float g1b = gam1[tid + 256], b1b = bet1[tid + 256];
    float g1z = gam1[512], b1z = bet1[512];
    float bias0 = bias[0];

    int ks = cta / 9, j = cta - ks * 9;   // scan role (cta < SCTA)
    int ty = tid >> 3, tx = tid & 7;      // gemm role (tid < 128)
    bool isX  = (cta < 72);               // x-region slice owner (ks 0..7)
    bool isSc = (cta < SCTA);
    u64t acc[8][4];
    float4 xr[8];                         // prefetched x rows (x-CTAs)

    for (int lev = 0; lev < DEPTH; lev++) {
        const float* Xr = (lev & 1) ? g_XB : g_XA;
        float*       Xw = (lev & 1) ? g_XA : g_XB;

        // -------- xW GEMM: 1152 tiles of 128x64, K=1024 ----------------------
        for (int tau = cta; tau < Tn * 9; tau += NCTA) {
            int t = tau / 9, jj = tau - t * 9;
            if (tid < 128) {
#pragma unroll
                for (int i = 0; i < 8; i++) {
                    acc[i][0] = 0ull; acc[i][1] = 0ull;
                    acc[i][2] = 0ull; acc[i][3] = 0ull;
                }
            }
            for (int ch = 0; ch < 16; ch++) {
                __syncthreads();
                stage_direct(sh_hT, Xr + ((size_t)t * Dn + ch * 64) * Bn);
                stage_B(sh_U, g_Wp, ch * 64, jj * 64);
                __syncthreads();
                if (tid < 128) gemm_chunk(acc, sh_hT, sh_U, ty, tx);
            }
            if (tid < 128)
                write_tile(acc, &g_XWraw[(size_t)(t * Bn) * NP + jj * 64], NP, ty, tx);
        }
        bar_arrive(kbar); bar_wait(base, kbar);

        // -------- LN of xW rows -> spre; zero g_h ----------------------------
        for (int r = cta; r < Tn * Bn; r += NCTA) {
            const float* row = &g_XWraw[(size_t)r * NP];
            float v0 = row[tid];
            float v1 = row[tid + 256];
            float v2 = (tid == 0) ? row[512] : 0.f;
            float s = v0 + v1 + v2;
            float q = v0 * v0 + v1 * v1 + v2 * v2;
#pragma unroll
            for (int o = 16; o > 0; o >>= 1) {
                s += __shfl_down_sync(0xffffffffu, s, o);
                q += __shfl_down_sync(0xffffffffu, q, o);
            }
            if ((tid & 31) == 0) { sh_red[tid >> 5] = s; sh_red[8 + (tid >> 5)] = q; }
            __syncthreads();
            if (tid == 0) {
                float S = 0.f, Q = 0.f;
#pragma unroll
                for (int w = 0; w < 8; w++) { S += sh_red[w]; Q += sh_red[8 + w]; }
                float mean = S * (1.f / (float)Nn);
                float var  = Q * (1.f / (float)Nn) - mean * mean;
                sh_sc[0] = mean;
                sh_sc[1] = 1.f / (sqrtf(var + EPSV) + EPSV);
            }
            __syncthreads();
            float mean = sh_sc[0], inv = sh_sc[1];
            float* o = &g_spre[(size_t)r * NP];
            o[tid]       = gam0[tid] * ((v0 - mean) * inv) + bet0[tid] + bias[tid];
            o[tid + 256] = gam0[tid + 256] * ((v1 - mean) * inv) + bet0[tid + 256] + bias[tid + 256];
            if (tid == 0)
                o[512] = gam0[512] * ((v2 - mean) * inv) + bet0[512] + bias[512];
            __syncthreads();
        }
        for (int i = gtid; i < Bn * Dn; i += nthr) g_h[i] = 0.f;
        bar_arrive(kbar); bar_wait(base, kbar);

        // -------- scan init: resident U, zero x-region h slice ----------------
        if (isSc) stage_B(sh_U, g_Up, ks * 64, j * 64);
        if (isX) {
            for (int i = tid; i < 64 * 132; i += NTHR) sh_hT[i] = 0.f;
        }
        // per-level register state (phase B, cta < Bn)
        float fk_c = 0.f, hv_c = 0.f;
        int prevmk = 0;
        float hT0 = 0.f, hT1 = 0.f;
        // phase-B prefetch regs
        float spv0 = 0.f, spv1 = 0.f, spv2 = 0.f, xt0 = 0.f, xt1 = 0.f;
        float fkpt = 0.f, fkpv = 0.f, hvpv = 0.f;
        int mval = 0;

        // ------------------------------ scan ---------------------------------
        for (int t = 0; t < Tn; t++) {
            // ---- phase A ----
            if (isX && t > 0) {
                if (tid < Bn) {
                    float2 gv = g_gates[tid];
                    sh_gA[tid] = gv.x; sh_gB[tid] = gv.y;
                }
                __syncthreads();
                int r = tid >> 2, bq = (tid & 3) << 5;
                float* hrow = sh_hT + r * 132 + bq;
                bool wr = (j == 0);
                float* xw = Xw + ((size_t)(t - 1) * Dn + ks * 64 + r) * Bn + bq;
#pragma unroll
                for (int q = 0; q < 8; q++) {
                    float4 h4 = *(float4*)(hrow + (q << 2));
                    float4 x4 = xr[q];
                    int b0 = bq + (q << 2);
                    h4.x = sh_gA[b0 + 0] * h4.x + sh_gB[b0 + 0] * x4.x;
                    h4.y = sh_gA[b0 + 1] * h4.y + sh_gB[b0 + 1] * x4.y;
                    h4.z = sh_gA[b0 + 2] * h4.z + sh_gB[b0 + 2] * x4.z;
                    h4.w = sh_gA[b0 + 3] * h4.w + sh_gB[b0 + 3] * x4.w;
                    *(float4*)(hrow + (q << 2)) = h4;
                    if (wr) *(float4*)(xw + (q << 2)) = h4;
                }
            }
            if (!isX && isSc) stage_T(sh_hT, g_h, Dn, ks * 64);
            __syncthreads();
            if (isSc && tid < 128) {
#pragma unroll
                for (int i = 0; i < 8; i++) {
                    acc[i][0] = 0ull; acc[i][1] = 0ull;
                    acc[i][2] = 0ull; acc[i][3] = 0ull;
                }
                gemm_chunk(acc, sh_hT, sh_U, ty, tx);
                write_tile(acc, &g_Gpart[(size_t)ks * NP + j * 64], KS * NP, ty, tx);
            }
            bar_arrive(kbar);
            // prefetch phase-B operands (barrier-independent)
            if (cta < Bn) {
                int b = cta;
                const float* sp = &g_spre[(size_t)(t * Bn + b) * NP];
                spv0 = sp[tid];
                spv1 = sp[tid + 256];
                xt0 = Xr[((size_t)t * Dn + 512 + tid) * Bn + b];
                xt1 = Xr[((size_t)t * Dn + 768 + tid) * Bn + b];
                if (tid == 0) {
                    spv2 = sp[512];
                    mval = mask[b * Tn + t];
                    fkpt = g_fkseq[t * Bn + b];
                    fkpv = (t + 1 < Tn) ? g_fkseq[(t + 1) * Bn + b] : 0.f;
                    hvpv = g_hvseq[t * Bn + b];
                }
            }
            bar_wait(base, kbar);

            // ---- phase B ----
            if (cta < Bn) {
                int b = cta;
                const float* gp = &g_Gpart[(size_t)b * KS * NP];
                float v0 = 0.f, v1 = 0.f, v2 = 0.f;
#pragma unroll
                for (int kq = 0; kq < KS; kq++) {
                    v0 += gp[kq * NP + tid];
                    v1 += gp[kq * NP + 256 + tid];
                    if (tid == 0) v2 += gp[kq * NP + 512];
                }
                float s = v0 + v1 + v2;
                float q = v0 * v0 + v1 * v1 + v2 * v2;
#pragma unroll
                for (int o = 16; o > 0; o >>= 1) {
                    s += __shfl_down_sync(0xffffffffu, s, o);
                    q += __shfl_down_sync(0xffffffffu, q, o);
                }
                if ((tid & 31) == 0) { sh_red[tid >> 5] = s; sh_red[8 + (tid >> 5)] = q; }
                __syncthreads();
                if (tid == 0) {
                    float S = 0.f, Q = 0.f;
#pragma unroll
                    for (int w = 0; w < 8; w++) { S += sh_red[w]; Q += sh_red[8 + w]; }
                    float mean = S * (1.f / (float)Nn);
                    float var  = Q * (1.f / (float)Nn) - mean * mean;
                    sh_sc[0] = mean;
                    sh_sc[1] = 1.f / (sqrtf(var + EPSV) + EPSV);
                }
                __syncthreads();
                float mean = sh_sc[0], inv = sh_sc[1];

                float s0 = spv0 + g1a * ((v0 - mean) * inv) + b1a;
                float s1 = spv1 + g1b * ((v1 - mean) * inv) + b1b;
                sh_s[tid]       = s0;
                sh_s[tid + 256] = s1;
                if (tid == 0)
                    sh_s[512] = spv2 + g1z * ((v2 - mean) * inv) + b1z;

                if (tid == 0) {
                    bool mk  = mval > 0;
                    bool mk2 = (t > 0) && (prevmk > 0) && !mk;
                    float sum2_0 = g1a * ((v0 - mean) * inv) + b1a - bias[0] - 0.f;
                    // NOTE: spre includes ln0+bias; sum2_0 must be raw LN1 col0:
                    sum2_0 = g1a * ((v0 - mean) * inv) + b1a;
                    float fk_both = fminf(fmaxf(0.2f * s0 + 0.5f, 0.f), 1.f);
                    float fk_t1   = fminf(fmaxf(0.2f * (sum2_0 + bias0) + 0.5f, 0.f), 1.f);
                    float fk = fkpt + (1.f - fkpt) *
                               (fk_c * fk_both + (1.f - fk_c) * fk_t1);
                    if (mk2) fk = 0.f;

                    float h_only = hv_c * fk * (fkpv + (1.f - fkpv) * (1.f - hvpv));
                    float x_only = hvpv * (1.f - fkpv) * (1.f - fk + fk * (1.f - hv_c));
                    float both   = (1.f - fkpv) * fk * hv_c * hvpv;
                    float hv = 1.f - (1.f - h_only) * (1.f - x_only) * (1.f - both);

                    float fk_out = mk ? fk : fk_c;
                    float hv_out = mk ? hv : hv_c;
                    if (mk2) fk_out = 0.f;
                    float mkf = mk ? 1.f : 0.f;

                    sh_sc[2] = h_only; sh_sc[3] = x_only;
                    sh_sc[4] = both;   sh_sc[5] = mkf;

                    g_gates[b] = make_float2(mkf * h_only + (1.f - mkf), mkf * x_only);
                    g_fkseq[t * Bn + b] = fk_out;
                    g_hvseq[t * Bn + b] = hv_out;
                    fk_c = fk_out; hv_c = hv_out; prevmk = mval;
                }
                __syncthreads();

                float h_only = sh_sc[2], x_only = sh_sc[3];
                float both = sh_sc[4], mkf = sh_sc[5];
                {
                    float hn0 = tanhf(sh_s[tid + 1]);
                    float nh0 = h_only * hT0 + x_only * xt0 + both * hn0;
                    nh0 = mkf * nh0 + (1.f - mkf) * hT0;
                    g_h[(size_t)b * Dn + 512 + tid] = nh0;
                    Xw[((size_t)t * Dn + 512 + tid) * Bn + b] = nh0;
                    hT0 = nh0;
                    float hn1 = tanhf(sh_s[tid + 257]);
                    float nh1 = h_only * hT1 + x_only * xt1 + both * hn1;
                    nh1 = mkf * nh1 + (1.f - mkf) * hT1;
                    g_h[(size_t)b * Dn + 768 + tid] = nh1;
                    Xw[((size_t)t * Dn + 768 + tid) * Bn + b] = nh1;
                    hT1 = nh1;
                }
            }
            bar_arrive(kbar);
            // prefetch x_t rows for next step's gate-apply (x-CTAs)
            if (isX) {
                int r = tid >> 2, bq = (tid & 3) << 5;
                const float* xs = Xr + ((size_t)t * Dn + ks * 64 + r) * Bn + bq;
#pragma unroll
                for (int q = 0; q < 8; q++)
                    xr[q] = *(const float4*)(xs + (q << 2));
            }
            bar_wait(base, kbar);
        }

        // -------- epilogue: final x-region h (t = 127) -----------------------
        if (isX && j == 0) {
            if (tid < Bn) {
                float2 gv = g_gates[tid];
                sh_gA[tid] = gv.x; sh_gB[tid] = gv.y;
            }
            __syncthreads();
            int r = tid >> 2, bq = (tid & 3) << 5;
            float* hrow = sh_hT + r * 132 + bq;
            float* xw = Xw + ((size_t)(Tn - 1) * Dn + ks * 64 + r) * Bn + bq;
#pragma unroll
            for (int q = 0; q < 8; q++) {
                float4 h4 = *(float4*)(hrow + (q << 2));
                float4 x4 = xr[q];
                int b0 = bq + (q << 2);
                h4.x = sh_gA[b0 + 0] * h4.x + sh_gB[b0 + 0] * x4.x;
                h4.y = sh_gA[b0 + 1] * h4.y + sh_gB[b0 + 1] * x4.y;
                h4.z = sh_gA[b0 + 2] * h4.z + sh_gB[b0 + 2] * x4.z;
                h4.w = sh_gA[b0 + 3] * h4.w + sh_gB[b0 + 3] * x4.w;
                *(float4*)(xw + (q << 2)) = h4;
            }
        }
        bar_arrive(kbar); bar_wait(base, kbar);
    }

    // ------------------------------ output ----------------------------------
    for (int i = gtid; i < Bn * Hn; i += nthr) {
        int b = i >> 9, jj = i & 511;
        out[i] = g_h[(size_t)b * Dn + In + jj];
    }
}

// ------------------------------- launcher -----------------------------------
extern "C" void kernel_launch(void* const* d_in, const int* in_sizes, int n_in,
                              void* d_out, int out_size) {
    const float* x      = (const float*)d_in[0];
    const int*   mask   = (const int*)d_in[1];
    const float* W      = (const float*)d_in[2];
    const float* U      = (const float*)d_in[3];
    const float* bias   = (const float*)d_in[4];
    const float* gammas = (const float*)d_in[5];
    const float* betas  = (const float*)d_in[6];
    float* out = (float*)d_out;

    hrnn_kernel<<<NCTA, NTHR>>>(x, mask, W, U, bias, gammas, betas, out);
}